// round 6
// baseline (speedup 1.0000x reference)
#include <cuda_runtime.h>

#define NN 100000
#define NE 1600000
#define IN_CH 128
#define HID 64
#define LAT 32

#define SCAN_BLK 512
#define SCAN_NB ((NN + SCAN_BLK - 1) / SCAN_BLK)   // 196

// Scratch (static __device__ — no allocations allowed)
__device__ int   g_stride;          // 1 = edge_index is int32, 2 = int64
__device__ int   g_deg[NN];
__device__ int   g_rowptr[NN + 1];
__device__ int   g_cursor[NN];
__device__ int   g_blocksums[SCAN_NB];
__device__ int   g_src[NE];
__device__ float g_nrm[NE];
__device__ float g_dis[NN];
__device__ float g_h1[NN * HID];   // gemm1 out; later reused as agg2 out
__device__ float g_h[NN * HID];    // relu(agg1 + b1)

// ---------------------------------------------------------------------------
// Detect dtype of edge_index: int64 values < 2^31 have all-zero odd words.
// For genuine int32 indices (random in [0, 100000)), P(32 consecutive odd
// words == 0) is ~0 — one ballot decides.
__global__ void k_detect(const int* __restrict__ ei) {
    int lane = threadIdx.x;
    int v = ei[2 * lane + 1];
    unsigned m = __ballot_sync(0xffffffffu, v != 0);
    if (lane == 0) g_stride = (m == 0u) ? 2 : 1;
}

__global__ void k_zero_deg() {
    int i = blockIdx.x * blockDim.x + threadIdx.x;
    if (i < NN) g_deg[i] = 0;
}

__global__ void k_count_deg(const int* __restrict__ ei) {
    int e = blockIdx.x * blockDim.x + threadIdx.x;
    if (e >= NE) return;
    int st = g_stride;
    int c = ei[(size_t)st * NE + (size_t)e * st];   // target node
    atomicAdd(&g_deg[c], 1);
}

// Per-block exclusive scan of g_deg -> g_rowptr (local), block totals out.
__global__ void k_scan_local() {
    __shared__ int s[SCAN_BLK];
    int t = threadIdx.x;
    int i = blockIdx.x * SCAN_BLK + t;
    int v = (i < NN) ? g_deg[i] : 0;
    s[t] = v;
    __syncthreads();
#pragma unroll
    for (int off = 1; off < SCAN_BLK; off <<= 1) {
        int add = (t >= off) ? s[t - off] : 0;
        __syncthreads();
        s[t] += add;
        __syncthreads();
    }
    if (i < NN) g_rowptr[i] = s[t] - v;   // exclusive
    if (t == SCAN_BLK - 1) g_blocksums[blockIdx.x] = s[t];
}

// Single-block exclusive scan of the block sums (196 values).
__global__ void k_scan_blocks() {
    __shared__ int s[256];
    int t = threadIdx.x;
    int v = (t < SCAN_NB) ? g_blocksums[t] : 0;
    s[t] = v;
    __syncthreads();
#pragma unroll
    for (int off = 1; off < 256; off <<= 1) {
        int add = (t >= off) ? s[t - off] : 0;
        __syncthreads();
        s[t] += add;
        __syncthreads();
    }
    if (t < SCAN_NB) g_blocksums[t] = s[t] - v;  // exclusive
}

// rowptr += block offset; cursor = rowptr; dis = rsqrt(deg + 1).
__global__ void k_finalize_csr() {
    int i = blockIdx.x * blockDim.x + threadIdx.x;
    if (i < NN) {
        int rp = g_rowptr[i] + g_blocksums[i >> 9];
        g_rowptr[i] = rp;
        g_cursor[i] = rp;
        g_dis[i] = rsqrtf((float)g_deg[i] + 1.0f);
    }
    if (i == 0) g_rowptr[NN] = NE;
}

__global__ void k_scatter(const int* __restrict__ ei) {
    int e = blockIdx.x * blockDim.x + threadIdx.x;
    if (e >= NE) return;
    int st = g_stride;
    int r = ei[(size_t)e * st];                     // source
    int c = ei[(size_t)st * NE + (size_t)e * st];   // target
    int pos = atomicAdd(&g_cursor[c], 1);
    g_src[pos] = r;
    g_nrm[pos] = g_dis[r] * g_dis[c];
}

// ---------------------------------------------------------------------------
// h1 = x @ W1  (100000x128 @ 128x64). 256 threads, 32 nodes/block.
__global__ void k_gemm1(const float* __restrict__ x, const float* __restrict__ W) {
    __shared__ alignas(16) float sW[IN_CH * HID];   // 32 KB, [k][c]
    __shared__ alignas(16) float sX[32 * IN_CH];    // 16 KB, swizzled [r][k^r]
    int tid = threadIdx.x;
    int node0 = blockIdx.x * 32;

    for (int i = tid; i < IN_CH * HID; i += 256) sW[i] = W[i];
    for (int i = tid; i < 32 * IN_CH; i += 256) {
        int r = i >> 7, k = i & 127;
        sX[r * IN_CH + (k ^ r)] = x[(size_t)(node0 + r) * IN_CH + k];
    }
    __syncthreads();

    int r = tid & 31;
    int c0 = (tid >> 5) * 8;
    float acc[8];
#pragma unroll
    for (int j = 0; j < 8; j++) acc[j] = 0.0f;

#pragma unroll 4
    for (int k = 0; k < IN_CH; k++) {
        float xv = sX[r * IN_CH + (k ^ r)];
        float4 w0 = *reinterpret_cast<const float4*>(&sW[k * HID + c0]);
        float4 w1 = *reinterpret_cast<const float4*>(&sW[k * HID + c0 + 4]);
        acc[0] += xv * w0.x; acc[1] += xv * w0.y;
        acc[2] += xv * w0.z; acc[3] += xv * w0.w;
        acc[4] += xv * w1.x; acc[5] += xv * w1.y;
        acc[6] += xv * w1.z; acc[7] += xv * w1.w;
    }

    size_t base = (size_t)(node0 + r) * HID + c0;
#pragma unroll
    for (int j = 0; j < 8; j++) g_h1[base + j] = acc[j];
}

// ---------------------------------------------------------------------------
// CSR aggregation: out[n] = dis[n]^2 * in[n] + sum_e nrm[e] * in[src[e]]
// 64 threads per node (1 channel each), 4 nodes per 256-thread block.
// 8-deep unrolled gather for MLP against L2 latency.
template <int DO_RELU>
__device__ __forceinline__ void agg_body(const float* __restrict__ hin,
                                         float* __restrict__ hout,
                                         const float* __restrict__ bias) {
    int node = blockIdx.x * 4 + (threadIdx.x >> 6);
    int ch = threadIdx.x & 63;
    if (node >= NN) return;

    float d = g_dis[node];
    float acc = d * d * hin[(size_t)node * HID + ch];

    const int* __restrict__ srcp = g_src;
    const float* __restrict__ nrmp = g_nrm;

    int e = g_rowptr[node];
    int end = g_rowptr[node + 1];

    float acc2 = 0.0f;
    for (; e + 7 < end; e += 8) {
        int s0 = srcp[e];
        int s1 = srcp[e + 1];
        int s2 = srcp[e + 2];
        int s3 = srcp[e + 3];
        int s4 = srcp[e + 4];
        int s5 = srcp[e + 5];
        int s6 = srcp[e + 6];
        int s7 = srcp[e + 7];
        float v0 = hin[(size_t)s0 * HID + ch];
        float v1 = hin[(size_t)s1 * HID + ch];
        float v2 = hin[(size_t)s2 * HID + ch];
        float v3 = hin[(size_t)s3 * HID + ch];
        float v4 = hin[(size_t)s4 * HID + ch];
        float v5 = hin[(size_t)s5 * HID + ch];
        float v6 = hin[(size_t)s6 * HID + ch];
        float v7 = hin[(size_t)s7 * HID + ch];
        float w0 = nrmp[e];
        float w1 = nrmp[e + 1];
        float w2 = nrmp[e + 2];
        float w3 = nrmp[e + 3];
        float w4 = nrmp[e + 4];
        float w5 = nrmp[e + 5];
        float w6 = nrmp[e + 6];
        float w7 = nrmp[e + 7];
        acc  += w0 * v0;
        acc2 += w1 * v1;
        acc  += w2 * v2;
        acc2 += w3 * v3;
        acc  += w4 * v4;
        acc2 += w5 * v5;
        acc  += w6 * v6;
        acc2 += w7 * v7;
    }
    for (; e < end; e++) {
        int s = srcp[e];
        acc += nrmp[e] * hin[(size_t)s * HID + ch];
    }
    acc += acc2;

    if (DO_RELU) {
        acc += bias[ch];
        acc = fmaxf(acc, 0.0f);
    }
    hout[(size_t)node * HID + ch] = acc;
}

__global__ void k_agg1(const float* __restrict__ bias) {
    agg_body<1>(g_h1, g_h, bias);
}

__global__ void k_agg2() {
    agg_body<0>(g_h, g_h1, nullptr);
}

// ---------------------------------------------------------------------------
// mu = agg2 @ Wmu + bmu ; lv = agg2 @ Wlv + blv  (agg2 lives in g_h1)
__global__ void k_gemm2(const float* __restrict__ Wmu, const float* __restrict__ bmu,
                        const float* __restrict__ Wlv, const float* __restrict__ blv,
                        float* __restrict__ out) {
    __shared__ alignas(16) float sW[HID * 64];  // [k][c], c<32 = Wmu, c>=32 = Wlv
    __shared__ alignas(16) float sA[32 * HID];  // swizzled
    __shared__ alignas(16) float sB[64];
    int tid = threadIdx.x;
    int node0 = blockIdx.x * 32;

    for (int i = tid; i < HID * 64; i += 256) {
        int k = i >> 6, c = i & 63;
        sW[i] = (c < 32) ? Wmu[k * LAT + c] : Wlv[k * LAT + (c - 32)];
    }
    if (tid < 64) sB[tid] = (tid < 32) ? bmu[tid] : blv[tid - 32];
    for (int i = tid; i < 32 * HID; i += 256) {
        int r = i >> 6, k = i & 63;
        sA[r * HID + (k ^ r)] = g_h1[(size_t)(node0 + r) * HID + k];
    }
    __syncthreads();

    int r = tid & 31;
    int c0 = (tid >> 5) * 8;
    float acc[8];
#pragma unroll
    for (int j = 0; j < 8; j++) acc[j] = 0.0f;

#pragma unroll 4
    for (int k = 0; k < HID; k++) {
        float av = sA[r * HID + (k ^ r)];
        float4 w0 = *reinterpret_cast<const float4*>(&sW[k * 64 + c0]);
        float4 w1 = *reinterpret_cast<const float4*>(&sW[k * 64 + c0 + 4]);
        acc[0] += av * w0.x; acc[1] += av * w0.y;
        acc[2] += av * w0.z; acc[3] += av * w0.w;
        acc[4] += av * w1.x; acc[5] += av * w1.y;
        acc[6] += av * w1.z; acc[7] += av * w1.w;
    }

    int node = node0 + r;
#pragma unroll
    for (int j = 0; j < 8; j++) {
        int c = c0 + j;
        float v = acc[j] + sB[c];
        if (c < 32)
            out[(size_t)node * LAT + c] = v;                            // mu
        else
            out[(size_t)NN * LAT + (size_t)node * LAT + (c - 32)] = v;  // logvar
    }
}

// ---------------------------------------------------------------------------
extern "C" void kernel_launch(void* const* d_in, const int* in_sizes, int n_in,
                              void* d_out, int out_size) {
    const float* x    = (const float*)d_in[0];
    const int*   ei   = (const int*)d_in[1];    // int32 or int64 (detected)
    const float* W1   = (const float*)d_in[2];
    const float* b1   = (const float*)d_in[3];
    const float* Wmu  = (const float*)d_in[4];
    const float* bmu  = (const float*)d_in[5];
    const float* Wlv  = (const float*)d_in[6];
    const float* blv  = (const float*)d_in[7];
    float*       out  = (float*)d_out;

    // CSR build
    k_detect<<<1, 32>>>(ei);
    k_zero_deg<<<(NN + 255) / 256, 256>>>();
    k_count_deg<<<(NE + 255) / 256, 256>>>(ei);
    k_scan_local<<<SCAN_NB, SCAN_BLK>>>();
    k_scan_blocks<<<1, 256>>>();
    k_finalize_csr<<<(NN + 255) / 256, 256>>>();
    k_scatter<<<(NE + 255) / 256, 256>>>(ei);

    // Dense + propagate
    k_gemm1<<<NN / 32, 256>>>(x, W1);                 // g_h1 = x@W1
    k_agg1<<<(NN + 3) / 4, 256>>>(b1);                // g_h = relu(P g_h1 + b1)
    k_agg2<<<(NN + 3) / 4, 256>>>();                  // g_h1 = P g_h
    k_gemm2<<<NN / 32, 256>>>(Wmu, bmu, Wlv, blv, out);
}

// round 7
// speedup vs baseline: 1.1322x; 1.1322x over previous
#include <cuda_runtime.h>

#define NN 100000
#define NE 1600000
#define IN_CH 128
#define HID 64
#define LAT 32

#define SCAN_BLK 512
#define SCAN_NB ((NN + SCAN_BLK - 1) / SCAN_BLK)   // 196

// Scratch (static __device__ — no allocations allowed)
__device__ int    g_stride;          // 1 = edge_index is int32, 2 = int64
__device__ int    g_deg[NN];
__device__ int    g_rowptr[NN + 1];
__device__ int    g_cursor[NN];
__device__ int    g_blocksums[SCAN_NB];
__device__ float2 g_edge[NE];        // {src_as_float_bits, norm}
__device__ float  g_dis[NN];
__device__ float  g_h1[NN * HID];    // gemm1 out; later reused as agg2 out
__device__ float  g_h[NN * HID];     // relu(agg1 + b1)

// ---------------------------------------------------------------------------
// Packed f32x2 FMA (Blackwell): acc += a * b on two lanes at once.
__device__ __forceinline__ void ffma2(unsigned long long& acc,
                                      unsigned long long a,
                                      unsigned long long b) {
    asm("fma.rn.f32x2 %0, %1, %2, %0;" : "+l"(acc) : "l"(a), "l"(b));
}
__device__ __forceinline__ unsigned long long pack2(float v) {
    unsigned long long r;
    asm("mov.b64 %0, {%1, %1};" : "=l"(r) : "f"(v));
    return r;
}
__device__ __forceinline__ void unpack2(unsigned long long p, float& lo, float& hi) {
    asm("mov.b64 {%0, %1}, %2;" : "=f"(lo), "=f"(hi) : "l"(p));
}

// ---------------------------------------------------------------------------
// Detect dtype of edge_index: int64 values < 2^31 have all-zero odd words.
__global__ void k_detect(const int* __restrict__ ei) {
    int lane = threadIdx.x;
    int v = ei[2 * lane + 1];
    unsigned m = __ballot_sync(0xffffffffu, v != 0);
    if (lane == 0) g_stride = (m == 0u) ? 2 : 1;
}

__global__ void k_zero_deg() {
    int i = blockIdx.x * blockDim.x + threadIdx.x;
    if (i < NN) g_deg[i] = 0;
}

__global__ void k_count_deg(const int* __restrict__ ei) {
    int e = blockIdx.x * blockDim.x + threadIdx.x;
    if (e >= NE) return;
    int st = g_stride;
    int c = ei[(size_t)st * NE + (size_t)e * st];   // target node
    atomicAdd(&g_deg[c], 1);
}

// Per-block exclusive scan of g_deg -> g_rowptr (local), block totals out.
__global__ void k_scan_local() {
    __shared__ int s[SCAN_BLK];
    int t = threadIdx.x;
    int i = blockIdx.x * SCAN_BLK + t;
    int v = (i < NN) ? g_deg[i] : 0;
    s[t] = v;
    __syncthreads();
#pragma unroll
    for (int off = 1; off < SCAN_BLK; off <<= 1) {
        int add = (t >= off) ? s[t - off] : 0;
        __syncthreads();
        s[t] += add;
        __syncthreads();
    }
    if (i < NN) g_rowptr[i] = s[t] - v;   // exclusive
    if (t == SCAN_BLK - 1) g_blocksums[blockIdx.x] = s[t];
}

// Single-block exclusive scan of the block sums (196 values).
__global__ void k_scan_blocks() {
    __shared__ int s[256];
    int t = threadIdx.x;
    int v = (t < SCAN_NB) ? g_blocksums[t] : 0;
    s[t] = v;
    __syncthreads();
#pragma unroll
    for (int off = 1; off < 256; off <<= 1) {
        int add = (t >= off) ? s[t - off] : 0;
        __syncthreads();
        s[t] += add;
        __syncthreads();
    }
    if (t < SCAN_NB) g_blocksums[t] = s[t] - v;  // exclusive
}

// rowptr += block offset; cursor = rowptr; dis = rsqrt(deg + 1).
__global__ void k_finalize_csr() {
    int i = blockIdx.x * blockDim.x + threadIdx.x;
    if (i < NN) {
        int rp = g_rowptr[i] + g_blocksums[i >> 9];
        g_rowptr[i] = rp;
        g_cursor[i] = rp;
        g_dis[i] = rsqrtf((float)g_deg[i] + 1.0f);
    }
    if (i == 0) g_rowptr[NN] = NE;
}

// Scatter edges into destination-sorted order as fused 8B records.
__global__ void k_scatter(const int* __restrict__ ei) {
    int e = blockIdx.x * blockDim.x + threadIdx.x;
    if (e >= NE) return;
    int st = g_stride;
    int r = ei[(size_t)e * st];                     // source
    int c = ei[(size_t)st * NE + (size_t)e * st];   // target
    int pos = atomicAdd(&g_cursor[c], 1);
    g_edge[pos] = make_float2(__int_as_float(r), g_dis[r] * g_dis[c]);
}

// ---------------------------------------------------------------------------
// h1 = x @ W1  (100000x128 @ 128x64). 256 threads, 32 nodes/block.
// Packed f32x2 accumulation: 4 FFMA2 per k-step per thread.
__global__ void k_gemm1(const float* __restrict__ x, const float* __restrict__ W) {
    __shared__ alignas(16) float sW[IN_CH * HID];   // 32 KB, [k][c]
    __shared__ alignas(16) float sX[32 * IN_CH];    // 16 KB, swizzled [r][k^r]
    int tid = threadIdx.x;
    int node0 = blockIdx.x * 32;

    for (int i = tid; i < IN_CH * HID; i += 256) sW[i] = W[i];
    for (int i = tid; i < 32 * IN_CH; i += 256) {
        int r = i >> 7, k = i & 127;
        sX[r * IN_CH + (k ^ r)] = x[(size_t)(node0 + r) * IN_CH + k];
    }
    __syncthreads();

    int r = tid & 31;
    int c0 = (tid >> 5) * 8;
    unsigned long long acc[4] = {0ull, 0ull, 0ull, 0ull};  // 4× packed f32x2

#pragma unroll 4
    for (int k = 0; k < IN_CH; k++) {
        unsigned long long xp = pack2(sX[r * IN_CH + (k ^ r)]);
        ulonglong2 w0 = *reinterpret_cast<const ulonglong2*>(&sW[k * HID + c0]);
        ulonglong2 w1 = *reinterpret_cast<const ulonglong2*>(&sW[k * HID + c0 + 4]);
        ffma2(acc[0], xp, w0.x);
        ffma2(acc[1], xp, w0.y);
        ffma2(acc[2], xp, w1.x);
        ffma2(acc[3], xp, w1.y);
    }

    size_t base = (size_t)(node0 + r) * HID + c0;
    float o[8];
#pragma unroll
    for (int j = 0; j < 4; j++) unpack2(acc[j], o[2 * j], o[2 * j + 1]);
#pragma unroll
    for (int j = 0; j < 8; j++) g_h1[base + j] = o[j];
}

// ---------------------------------------------------------------------------
// CSR aggregation: out[n] = dis[n]^2 * in[n] + sum_e nrm[e] * in[src[e]]
// WARP per node: 32 lanes × float2 = 64 channels. 8 nodes / 256-thread block.
// Per edge: ONE broadcast LDG.64 (edge record) + ONE gather LDG.64 per warp.
template <int DO_RELU>
__device__ __forceinline__ void agg_body(const float2* __restrict__ hin2,
                                         float2* __restrict__ hout2,
                                         const float2* __restrict__ bias2) {
    int node = blockIdx.x * 8 + (threadIdx.x >> 5);   // 12500*8 == NN exactly
    int lane = threadIdx.x & 31;

    float d = g_dis[node];
    float2 self = hin2[node * 32 + lane];
    float acx = d * d * self.x;
    float acy = d * d * self.y;
    float bcx = 0.0f, bcy = 0.0f;

    const float2* __restrict__ ed = g_edge;
    int e = g_rowptr[node];
    int end = g_rowptr[node + 1];

    for (; e + 7 < end; e += 8) {
        float2 e0 = ed[e],     e1 = ed[e + 1], e2 = ed[e + 2], e3 = ed[e + 3];
        float2 e4 = ed[e + 4], e5 = ed[e + 5], e6 = ed[e + 6], e7 = ed[e + 7];
        float2 v0 = hin2[(size_t)__float_as_int(e0.x) * 32 + lane];
        float2 v1 = hin2[(size_t)__float_as_int(e1.x) * 32 + lane];
        float2 v2 = hin2[(size_t)__float_as_int(e2.x) * 32 + lane];
        float2 v3 = hin2[(size_t)__float_as_int(e3.x) * 32 + lane];
        float2 v4 = hin2[(size_t)__float_as_int(e4.x) * 32 + lane];
        float2 v5 = hin2[(size_t)__float_as_int(e5.x) * 32 + lane];
        float2 v6 = hin2[(size_t)__float_as_int(e6.x) * 32 + lane];
        float2 v7 = hin2[(size_t)__float_as_int(e7.x) * 32 + lane];
        acx += e0.y * v0.x; acy += e0.y * v0.y;
        bcx += e1.y * v1.x; bcy += e1.y * v1.y;
        acx += e2.y * v2.x; acy += e2.y * v2.y;
        bcx += e3.y * v3.x; bcy += e3.y * v3.y;
        acx += e4.y * v4.x; acy += e4.y * v4.y;
        bcx += e5.y * v5.x; bcy += e5.y * v5.y;
        acx += e6.y * v6.x; acy += e6.y * v6.y;
        bcx += e7.y * v7.x; bcy += e7.y * v7.y;
    }
    for (; e < end; e++) {
        float2 er = ed[e];
        float2 v = hin2[(size_t)__float_as_int(er.x) * 32 + lane];
        acx += er.y * v.x;
        acy += er.y * v.y;
    }
    acx += bcx;
    acy += bcy;

    if (DO_RELU) {
        float2 b = bias2[lane];
        acx = fmaxf(acx + b.x, 0.0f);
        acy = fmaxf(acy + b.y, 0.0f);
    }
    hout2[node * 32 + lane] = make_float2(acx, acy);
}

__global__ void k_agg1(const float* __restrict__ bias) {
    agg_body<1>(reinterpret_cast<const float2*>(g_h1),
                reinterpret_cast<float2*>(g_h),
                reinterpret_cast<const float2*>(bias));
}

__global__ void k_agg2() {
    agg_body<0>(reinterpret_cast<const float2*>(g_h),
                reinterpret_cast<float2*>(g_h1), nullptr);
}

// ---------------------------------------------------------------------------
// mu = agg2 @ Wmu + bmu ; lv = agg2 @ Wlv + blv  (agg2 lives in g_h1)
__global__ void k_gemm2(const float* __restrict__ Wmu, const float* __restrict__ bmu,
                        const float* __restrict__ Wlv, const float* __restrict__ blv,
                        float* __restrict__ out) {
    __shared__ alignas(16) float sW[HID * 64];  // [k][c], c<32 = Wmu, c>=32 = Wlv
    __shared__ alignas(16) float sA[32 * HID];  // swizzled
    __shared__ alignas(16) float sB[64];
    int tid = threadIdx.x;
    int node0 = blockIdx.x * 32;

    for (int i = tid; i < HID * 64; i += 256) {
        int k = i >> 6, c = i & 63;
        sW[i] = (c < 32) ? Wmu[k * LAT + c] : Wlv[k * LAT + (c - 32)];
    }
    if (tid < 64) sB[tid] = (tid < 32) ? bmu[tid] : blv[tid - 32];
    for (int i = tid; i < 32 * HID; i += 256) {
        int r = i >> 6, k = i & 63;
        sA[r * HID + (k ^ r)] = g_h1[(size_t)(node0 + r) * HID + k];
    }
    __syncthreads();

    int r = tid & 31;
    int c0 = (tid >> 5) * 8;
    unsigned long long acc[4] = {0ull, 0ull, 0ull, 0ull};

#pragma unroll 4
    for (int k = 0; k < HID; k++) {
        unsigned long long ap = pack2(sA[r * HID + (k ^ r)]);
        ulonglong2 w0 = *reinterpret_cast<const ulonglong2*>(&sW[k * 64 + c0]);
        ulonglong2 w1 = *reinterpret_cast<const ulonglong2*>(&sW[k * 64 + c0 + 4]);
        ffma2(acc[0], ap, w0.x);
        ffma2(acc[1], ap, w0.y);
        ffma2(acc[2], ap, w1.x);
        ffma2(acc[3], ap, w1.y);
    }

    int node = node0 + r;
    float o[8];
#pragma unroll
    for (int j = 0; j < 4; j++) unpack2(acc[j], o[2 * j], o[2 * j + 1]);
#pragma unroll
    for (int j = 0; j < 8; j++) {
        int c = c0 + j;
        float v = o[j] + sB[c];
        if (c < 32)
            out[(size_t)node * LAT + c] = v;                            // mu
        else
            out[(size_t)NN * LAT + (size_t)node * LAT + (c - 32)] = v;  // logvar
    }
}

// ---------------------------------------------------------------------------
extern "C" void kernel_launch(void* const* d_in, const int* in_sizes, int n_in,
                              void* d_out, int out_size) {
    const float* x    = (const float*)d_in[0];
    const int*   ei   = (const int*)d_in[1];    // int32 or int64 (detected)
    const float* W1   = (const float*)d_in[2];
    const float* b1   = (const float*)d_in[3];
    const float* Wmu  = (const float*)d_in[4];
    const float* bmu  = (const float*)d_in[5];
    const float* Wlv  = (const float*)d_in[6];
    const float* blv  = (const float*)d_in[7];
    float*       out  = (float*)d_out;

    // CSR build
    k_detect<<<1, 32>>>(ei);
    k_zero_deg<<<(NN + 255) / 256, 256>>>();
    k_count_deg<<<(NE + 255) / 256, 256>>>(ei);
    k_scan_local<<<SCAN_NB, SCAN_BLK>>>();
    k_scan_blocks<<<1, 256>>>();
    k_finalize_csr<<<(NN + 255) / 256, 256>>>();
    k_scatter<<<(NE + 255) / 256, 256>>>(ei);

    // Dense + propagate
    k_gemm1<<<NN / 32, 256>>>(x, W1);                 // g_h1 = x@W1
    k_agg1<<<NN / 8, 256>>>(b1);                      // g_h = relu(P g_h1 + b1)
    k_agg2<<<NN / 8, 256>>>();                        // g_h1 = P g_h
    k_gemm2<<<NN / 32, 256>>>(Wmu, bmu, Wlv, blv, out);
}

// round 8
// speedup vs baseline: 1.3178x; 1.1640x over previous
#include <cuda_runtime.h>
#include <cuda_fp16.h>

#define NN 100000
#define NE 1600000
#define IN_CH 128
#define HID 64
#define LAT 32

#define SCAN_BLK 512
#define SCAN_NB ((NN + SCAN_BLK - 1) / SCAN_BLK)   // 196

// Scratch (static __device__ — no allocations allowed)
__device__ int     g_stride;          // 1 = edge_index is int32, 2 = int64
__device__ int     g_deg[NN];
__device__ int     g_rowptr[NN + 1];
__device__ int     g_cursor[NN];
__device__ int     g_blocksums[SCAN_NB];
__device__ float2  g_edge[NE];        // {src_as_float_bits, norm}
__device__ float   g_dis[NN];
__device__ __half2 g_ha[NN * 32];     // h1 = x@W1 in fp16 (agg1 gather input)
__device__ __half2 g_hb[NN * 32];     // relu(agg1+b1) in fp16 (agg2 gather input)
__device__ float   g_f[NN * HID];     // agg2 output fp32 (gemm2 input)

struct alignas(16) H8 { __half2 h[4]; };

// ---------------------------------------------------------------------------
// Packed f32x2 FMA (Blackwell).
__device__ __forceinline__ void ffma2(unsigned long long& acc,
                                      unsigned long long a,
                                      unsigned long long b) {
    asm("fma.rn.f32x2 %0, %1, %2, %0;" : "+l"(acc) : "l"(a), "l"(b));
}
__device__ __forceinline__ unsigned long long pack2(float v) {
    unsigned long long r;
    asm("mov.b64 %0, {%1, %1};" : "=l"(r) : "f"(v));
    return r;
}
__device__ __forceinline__ void unpack2(unsigned long long p, float& lo, float& hi) {
    asm("mov.b64 {%0, %1}, %2;" : "=f"(lo), "=f"(hi) : "l"(p));
}

// ---------------------------------------------------------------------------
// Zero degree array; block 0 warp 0 also detects edge_index dtype:
// int64 values < 2^31 have all-zero odd 32-bit words.
__global__ void k_zero_detect(const int* __restrict__ ei) {
    int i = blockIdx.x * blockDim.x + threadIdx.x;
    if (i < NN) g_deg[i] = 0;
    if (blockIdx.x == 0 && threadIdx.x < 32) {
        int lane = threadIdx.x;
        int v = ei[2 * lane + 1];
        unsigned m = __ballot_sync(0xffffffffu, v != 0);
        if (lane == 0) g_stride = (m == 0u) ? 2 : 1;
    }
}

__global__ void k_count_deg(const int* __restrict__ ei) {
    int e = blockIdx.x * blockDim.x + threadIdx.x;
    if (e >= NE) return;
    int st = g_stride;
    int c = ei[(size_t)st * NE + (size_t)e * st];   // target node
    atomicAdd(&g_deg[c], 1);
}

// Per-block exclusive scan of g_deg -> g_rowptr (local), block totals out.
__global__ void k_scan_local() {
    __shared__ int s[SCAN_BLK];
    int t = threadIdx.x;
    int i = blockIdx.x * SCAN_BLK + t;
    int v = (i < NN) ? g_deg[i] : 0;
    s[t] = v;
    __syncthreads();
#pragma unroll
    for (int off = 1; off < SCAN_BLK; off <<= 1) {
        int add = (t >= off) ? s[t - off] : 0;
        __syncthreads();
        s[t] += add;
        __syncthreads();
    }
    if (i < NN) g_rowptr[i] = s[t] - v;   // exclusive
    if (t == SCAN_BLK - 1) g_blocksums[blockIdx.x] = s[t];
}

// Single-block exclusive scan of the block sums (196 values).
__global__ void k_scan_blocks() {
    __shared__ int s[256];
    int t = threadIdx.x;
    int v = (t < SCAN_NB) ? g_blocksums[t] : 0;
    s[t] = v;
    __syncthreads();
#pragma unroll
    for (int off = 1; off < 256; off <<= 1) {
        int add = (t >= off) ? s[t - off] : 0;
        __syncthreads();
        s[t] += add;
        __syncthreads();
    }
    if (t < SCAN_NB) g_blocksums[t] = s[t] - v;  // exclusive
}

// rowptr += block offset; cursor = rowptr; dis = rsqrt(deg + 1).
__global__ void k_finalize_csr() {
    int i = blockIdx.x * blockDim.x + threadIdx.x;
    if (i < NN) {
        int rp = g_rowptr[i] + g_blocksums[i >> 9];
        g_rowptr[i] = rp;
        g_cursor[i] = rp;
        g_dis[i] = rsqrtf((float)g_deg[i] + 1.0f);
    }
    if (i == 0) g_rowptr[NN] = NE;
}

// Scatter edges into destination-sorted order as fused 8B records.
__global__ void k_scatter(const int* __restrict__ ei) {
    int e = blockIdx.x * blockDim.x + threadIdx.x;
    if (e >= NE) return;
    int st = g_stride;
    int r = ei[(size_t)e * st];                     // source
    int c = ei[(size_t)st * NE + (size_t)e * st];   // target
    int pos = atomicAdd(&g_cursor[c], 1);
    g_edge[pos] = make_float2(__int_as_float(r), g_dis[r] * g_dis[c]);
}

// ---------------------------------------------------------------------------
// h1 = x @ W1  (100000x128 @ 128x64), output fp16 to g_ha.
// 256 threads; each block does 64 rows in TWO 32-row phases sharing one W load.
__global__ void k_gemm1(const float* __restrict__ x, const float* __restrict__ W) {
    __shared__ alignas(16) float sW[IN_CH * HID];   // 32 KB, [k][c]
    __shared__ alignas(16) float sX[32 * IN_CH];    // 16 KB, swizzled [r][k^r]
    int tid = threadIdx.x;
    int base0 = blockIdx.x * 64;

    for (int i = tid; i < IN_CH * HID; i += 256) sW[i] = W[i];

    int r = tid & 31;
    int c0 = (tid >> 5) * 8;

#pragma unroll
    for (int phase = 0; phase < 2; phase++) {
        int node0 = base0 + phase * 32;
        __syncthreads();   // sW ready (phase 0) / previous compute done (phase 1)
        for (int i = tid; i < 32 * IN_CH; i += 256) {
            int rr = i >> 7, k = i & 127;
            int row = node0 + rr;
            if (row >= NN) row = NN - 1;            // safe pad (store guarded)
            sX[rr * IN_CH + (k ^ rr)] = x[(size_t)row * IN_CH + k];
        }
        __syncthreads();

        unsigned long long acc[4] = {0ull, 0ull, 0ull, 0ull};
#pragma unroll 4
        for (int k = 0; k < IN_CH; k++) {
            unsigned long long xp = pack2(sX[r * IN_CH + (k ^ r)]);
            ulonglong2 w0 = *reinterpret_cast<const ulonglong2*>(&sW[k * HID + c0]);
            ulonglong2 w1 = *reinterpret_cast<const ulonglong2*>(&sW[k * HID + c0 + 4]);
            ffma2(acc[0], xp, w0.x);
            ffma2(acc[1], xp, w0.y);
            ffma2(acc[2], xp, w1.x);
            ffma2(acc[3], xp, w1.y);
        }

        int node = node0 + r;
        if (node < NN) {
            float o[8];
#pragma unroll
            for (int j = 0; j < 4; j++) unpack2(acc[j], o[2 * j], o[2 * j + 1]);
            H8 v;
#pragma unroll
            for (int j = 0; j < 4; j++)
                v.h[j] = __floats2half2_rn(o[2 * j], o[2 * j + 1]);
            *reinterpret_cast<H8*>(&g_ha[(size_t)node * 32 + (c0 >> 1)]) = v;
        }
    }
}

// ---------------------------------------------------------------------------
// CSR aggregation: out[n] = dis[n]^2 * in[n] + sum_e nrm[e] * in[src[e]]
// WARP per node: 32 lanes × half2 = 64 channels; fp32 accumulation.
// Per edge: ONE broadcast LDG.64 (record) + ONE 128B-line gather LDG.32/warp.
// MODE 1: +bias, relu, half2 out.  MODE 0: float2 out.
template <int MODE>
__device__ __forceinline__ void agg_body(const __half2* __restrict__ hin,
                                         __half2* __restrict__ hout_h,
                                         float2* __restrict__ hout_f,
                                         const float2* __restrict__ bias2) {
    int node = blockIdx.x * 8 + (threadIdx.x >> 5);   // 12500*8 == NN exactly
    int lane = threadIdx.x & 31;

    float d = g_dis[node];
    float2 self = __half22float2(hin[node * 32 + lane]);
    float acx = d * d * self.x;
    float acy = d * d * self.y;
    float bcx = 0.0f, bcy = 0.0f;

    const float2* __restrict__ ed = g_edge;
    int e = g_rowptr[node];
    int end = g_rowptr[node + 1];

    for (; e + 7 < end; e += 8) {
        float2 e0 = ed[e],     e1 = ed[e + 1], e2 = ed[e + 2], e3 = ed[e + 3];
        float2 e4 = ed[e + 4], e5 = ed[e + 5], e6 = ed[e + 6], e7 = ed[e + 7];
        float2 v0 = __half22float2(hin[(size_t)__float_as_int(e0.x) * 32 + lane]);
        float2 v1 = __half22float2(hin[(size_t)__float_as_int(e1.x) * 32 + lane]);
        float2 v2 = __half22float2(hin[(size_t)__float_as_int(e2.x) * 32 + lane]);
        float2 v3 = __half22float2(hin[(size_t)__float_as_int(e3.x) * 32 + lane]);
        float2 v4 = __half22float2(hin[(size_t)__float_as_int(e4.x) * 32 + lane]);
        float2 v5 = __half22float2(hin[(size_t)__float_as_int(e5.x) * 32 + lane]);
        float2 v6 = __half22float2(hin[(size_t)__float_as_int(e6.x) * 32 + lane]);
        float2 v7 = __half22float2(hin[(size_t)__float_as_int(e7.x) * 32 + lane]);
        acx += e0.y * v0.x; acy += e0.y * v0.y;
        bcx += e1.y * v1.x; bcy += e1.y * v1.y;
        acx += e2.y * v2.x; acy += e2.y * v2.y;
        bcx += e3.y * v3.x; bcy += e3.y * v3.y;
        acx += e4.y * v4.x; acy += e4.y * v4.y;
        bcx += e5.y * v5.x; bcy += e5.y * v5.y;
        acx += e6.y * v6.x; acy += e6.y * v6.y;
        bcx += e7.y * v7.x; bcy += e7.y * v7.y;
    }
    for (; e < end; e++) {
        float2 er = ed[e];
        float2 v = __half22float2(hin[(size_t)__float_as_int(er.x) * 32 + lane]);
        acx += er.y * v.x;
        acy += er.y * v.y;
    }
    acx += bcx;
    acy += bcy;

    if (MODE == 1) {
        float2 b = bias2[lane];
        acx = fmaxf(acx + b.x, 0.0f);
        acy = fmaxf(acy + b.y, 0.0f);
        hout_h[node * 32 + lane] = __floats2half2_rn(acx, acy);
    } else {
        hout_f[node * 32 + lane] = make_float2(acx, acy);
    }
}

__global__ void k_agg1(const float* __restrict__ bias) {
    agg_body<1>(g_ha, g_hb, nullptr, reinterpret_cast<const float2*>(bias));
}

__global__ void k_agg2() {
    agg_body<0>(g_hb, nullptr, reinterpret_cast<float2*>(g_f), nullptr);
}

// ---------------------------------------------------------------------------
// mu = agg2 @ Wmu + bmu ; lv = agg2 @ Wlv + blv  (agg2 fp32 in g_f)
// 256 threads, 64 rows/block, 16 cols/thread.
__global__ void k_gemm2(const float* __restrict__ Wmu, const float* __restrict__ bmu,
                        const float* __restrict__ Wlv, const float* __restrict__ blv,
                        float* __restrict__ out) {
    __shared__ alignas(16) float sW[HID * 64];  // 16 KB: [k][c], c<32=Wmu, c>=32=Wlv
    __shared__ alignas(16) float sA[64 * HID];  // 16 KB, swizzled
    __shared__ alignas(16) float sB[64];
    int tid = threadIdx.x;
    int node0 = blockIdx.x * 64;

    for (int i = tid; i < HID * 64; i += 256) {
        int k = i >> 6, c = i & 63;
        sW[i] = (c < 32) ? Wmu[k * LAT + c] : Wlv[k * LAT + (c - 32)];
    }
    if (tid < 64) sB[tid] = (tid < 32) ? bmu[tid] : blv[tid - 32];
    for (int i = tid; i < 64 * HID; i += 256) {
        int r = i >> 6, k = i & 63;
        int row = node0 + r;
        if (row >= NN) row = NN - 1;               // safe pad (store guarded)
        sA[r * HID + (k ^ (r & 31))] = g_f[(size_t)row * HID + k];
    }
    __syncthreads();

    int r = tid & 63;
    int c0 = (tid >> 6) * 16;
    unsigned long long acc[8] = {0ull, 0ull, 0ull, 0ull, 0ull, 0ull, 0ull, 0ull};

#pragma unroll 4
    for (int k = 0; k < HID; k++) {
        unsigned long long ap = pack2(sA[r * HID + (k ^ (r & 31))]);
        ulonglong2 w0 = *reinterpret_cast<const ulonglong2*>(&sW[k * 64 + c0]);
        ulonglong2 w1 = *reinterpret_cast<const ulonglong2*>(&sW[k * 64 + c0 + 4]);
        ulonglong2 w2 = *reinterpret_cast<const ulonglong2*>(&sW[k * 64 + c0 + 8]);
        ulonglong2 w3 = *reinterpret_cast<const ulonglong2*>(&sW[k * 64 + c0 + 12]);
        ffma2(acc[0], ap, w0.x);
        ffma2(acc[1], ap, w0.y);
        ffma2(acc[2], ap, w1.x);
        ffma2(acc[3], ap, w1.y);
        ffma2(acc[4], ap, w2.x);
        ffma2(acc[5], ap, w2.y);
        ffma2(acc[6], ap, w3.x);
        ffma2(acc[7], ap, w3.y);
    }

    int node = node0 + r;
    if (node >= NN) return;
    float o[16];
#pragma unroll
    for (int j = 0; j < 8; j++) unpack2(acc[j], o[2 * j], o[2 * j + 1]);
#pragma unroll
    for (int j = 0; j < 16; j++) {
        int c = c0 + j;
        float v = o[j] + sB[c];
        if (c < 32)
            out[(size_t)node * LAT + c] = v;                            // mu
        else
            out[(size_t)NN * LAT + (size_t)node * LAT + (c - 32)] = v;  // logvar
    }
}

// ---------------------------------------------------------------------------
extern "C" void kernel_launch(void* const* d_in, const int* in_sizes, int n_in,
                              void* d_out, int out_size) {
    const float* x    = (const float*)d_in[0];
    const int*   ei   = (const int*)d_in[1];    // int32 or int64 (detected)
    const float* W1   = (const float*)d_in[2];
    const float* b1   = (const float*)d_in[3];
    const float* Wmu  = (const float*)d_in[4];
    const float* bmu  = (const float*)d_in[5];
    const float* Wlv  = (const float*)d_in[6];
    const float* blv  = (const float*)d_in[7];
    float*       out  = (float*)d_out;

    // CSR build
    k_zero_detect<<<(NN + 255) / 256, 256>>>(ei);
    k_count_deg<<<(NE + 255) / 256, 256>>>(ei);
    k_scan_local<<<SCAN_NB, SCAN_BLK>>>();
    k_scan_blocks<<<1, 256>>>();
    k_finalize_csr<<<(NN + 255) / 256, 256>>>();
    k_scatter<<<(NE + 255) / 256, 256>>>(ei);

    // Dense + propagate
    k_gemm1<<<(NN + 63) / 64, 256>>>(x, W1);          // g_ha = fp16(x@W1)
    k_agg1<<<NN / 8, 256>>>(b1);                      // g_hb = fp16(relu(P ha + b1))
    k_agg2<<<NN / 8, 256>>>();                        // g_f  = P hb (fp32)
    k_gemm2<<<(NN + 63) / 64, 256>>>(Wmu, bmu, Wlv, blv, out);
}